// round 14
// baseline (speedup 1.0000x reference)
#include <cuda_runtime.h>
#include <math.h>
#include <stdint.h>

#define BNB   8
#define C     64
#define NPTS  16384
#define KNBR  32
#define CN    256
#define CLEN  32
#define NCURVE (BNB*CN)     // 2048
#define WBLK  128           // walk grid blocks (co-resident on 148 SMs)
#define WTPB  512
#define WPB   16            // warps (=curves) per block
#define PVP   68            // padded pv row

#define SCALE_S 17179869184.0      // 2^34 for sums
#define SCALE_Q 1073741824.0       // 2^30 for sums of squares

// ---------------- device scratch (no allocations allowed) ----------------
__device__ float  g_xw[(size_t)BNB*NPTS*C];   // point-major gated features [bn*n][c]
__device__ float  g_att[BNB*NPTS];
__device__ int    g_start[NCURVE];
__device__ float  g_mm[BNB*2*CN];             // raw momentum logits (scrambled softmax)
__device__ float  g_curve[NCURVE][CLEN][C];   // curve-major staging for output
// 64 reduction slots: agent(t)->slot 2t, momentum(t)->slot 2t-1
__device__ unsigned long long g_rsum[64][4][32];  // entry stride 256B
__device__ unsigned int       g_rcnt[64][64];     // cnt at [s][0]
__device__ float              g_rcoef[64][32];    // published BN coefs (one line)
__device__ int                g_rflag[64][32];    // publish flag (one line)

// ---------------- helpers ----------------
__device__ __forceinline__ float warpsum(float v) {
    #pragma unroll
    for (int o = 16; o; o >>= 1) v += __shfl_down_sync(0xFFFFFFFFu, v, o);
    return __shfl_sync(0xFFFFFFFFu, v, 0);
}
__device__ __forceinline__ void warpsum3(float& a, float& b, float& c) {
    #pragma unroll
    for (int o = 16; o; o >>= 1) {
        a += __shfl_down_sync(0xFFFFFFFFu, a, o);
        b += __shfl_down_sync(0xFFFFFFFFu, b, o);
        c += __shfl_down_sync(0xFFFFFFFFu, c, o);
    }
    a = __shfl_sync(0xFFFFFFFFu, a, 0);
    b = __shfl_sync(0xFFFFFFFFu, b, 0);
    c = __shfl_sync(0xFFFFFFFFu, c, 0);
}
__device__ __forceinline__ void warpsumd2(double& a, double& b) {
    #pragma unroll
    for (int o = 16; o; o >>= 1) {
        a += __shfl_down_sync(0xFFFFFFFFu, a, o);
        b += __shfl_down_sync(0xFFFFFFFFu, b, o);
    }
    a = __shfl_sync(0xFFFFFFFFu, a, 0);
    b = __shfl_sync(0xFFFFFFFFu, b, 0);
}
__device__ __forceinline__ void stg_rel_s32(int* p, int v) {
    asm volatile("st.release.gpu.global.s32 [%0], %1;" :: "l"(p), "r"(v) : "memory");
}
__device__ __forceinline__ int ldg_acq_s32(int* p) {
    int v; asm volatile("ld.acquire.gpu.global.s32 %0, [%1];" : "=r"(v) : "l"(p) : "memory");
    return v;
}
__device__ __forceinline__ float ldg_rlx_f32(const float* p) {
    float v; asm volatile("ld.relaxed.gpu.global.f32 %0, [%1];" : "=f"(v) : "l"(p) : "memory");
    return v;
}
__device__ __forceinline__ void stg_rlx_f32(float* p, float v) {
    asm volatile("st.relaxed.gpu.global.f32 [%0], %1;" :: "l"(p), "f"(v) : "memory");
}
__device__ __forceinline__ unsigned long long ldg_rlx_u64(const unsigned long long* p) {
    unsigned long long v;
    asm volatile("ld.relaxed.gpu.global.u64 %0, [%1];" : "=l"(v) : "l"(p) : "memory");
    return v;
}

// ---------------- kernel 1: x_att + transposed gated features (+ slot zeroing) ----
__global__ void k_xw(const float* __restrict__ x, const float* __restrict__ att_w) {
    __shared__ float sx[64][65];
    __shared__ float satt[64];
    __shared__ float sw[64];
    const int tid = threadIdx.x;
    const int b  = blockIdx.x >> 8;
    const int n0 = (blockIdx.x & 255) * 64;
    if (blockIdx.x < 64) {
        int s = blockIdx.x;
        if (tid < 4)       g_rsum[s][tid][0] = 0ull;
        else if (tid == 4) g_rcnt[s][0] = 0u;
        else if (tid == 5) g_rflag[s][0] = 0;
    }
    if (tid < 64) sw[tid] = att_w[tid];
    for (int i = tid; i < 64 * 64; i += 256) {
        int c = i >> 6, nn = i & 63;
        sx[c][nn] = x[((size_t)(b * C + c)) * NPTS + n0 + nn];
    }
    __syncthreads();
    if (tid < 64) {
        float s = 0.f;
        #pragma unroll
        for (int c = 0; c < 64; ++c) s += sx[c][tid] * sw[c];
        float a = 1.f / (1.f + expf(-s));
        satt[tid] = a;
        g_att[b * NPTS + n0 + tid] = a;
    }
    __syncthreads();
    for (int i = tid; i < 64 * 64; i += 256) {
        int nn = i >> 6, c = i & 63;
        g_xw[((size_t)(b * NPTS + n0 + nn)) * C + c] = sx[c][nn] * satt[nn];
    }
}

// -------- kernel 2: exact sorted top-256 per batch (chunk sort + max tournament) ----
__global__ void k_topk() {
    extern __shared__ unsigned long long sk[];
    const int tid = threadIdx.x;
    const int b = blockIdx.x;
    const int T = 1024;
    for (int i = tid; i < NPTS; i += T) {
        unsigned u = __float_as_uint(g_att[b * NPTS + i]);
        u = (u & 0x80000000u) ? ~u : (u | 0x80000000u);
        sk[i] = ((unsigned long long)u << 32) | (unsigned)(NPTS - 1 - i);
    }
    __syncthreads();
    for (int k = 2; k <= 256; k <<= 1) {
        for (int j = k >> 1; j > 0; j >>= 1) {
            for (int i = tid; i < NPTS; i += T) {
                int ixj = i ^ j;
                if (ixj > i) {
                    bool up = ((i & k) == 0);
                    unsigned long long a = sk[i], c = sk[ixj];
                    if ((a > c) == up) { sk[i] = c; sk[ixj] = a; }
                }
            }
            __syncthreads();
        }
    }
    int S = NPTS;
    while (S > 256) {
        int half = S >> 1;
        unsigned long long v[8];
        int cnt = 0;
        for (int i = tid; i < half; i += T) {
            int p = i >> 8, o = i & 255;
            unsigned long long a = sk[(2 * p) * 256 + o];
            unsigned long long c = sk[(2 * p + 1) * 256 + o];
            v[cnt++] = a > c ? a : c;
        }
        __syncthreads();
        cnt = 0;
        for (int i = tid; i < half; i += T) sk[i] = v[cnt++];
        __syncthreads();
        for (int j = 128; j > 0; j >>= 1) {
            for (int i = tid; i < half; i += T) {
                int ixj = i ^ j;
                if (ixj > i) {
                    bool up = ((i & 256) == 0);
                    unsigned long long a = sk[i], c = sk[ixj];
                    if ((a > c) == up) { sk[i] = c; sk[ixj] = a; }
                }
            }
            __syncthreads();
        }
        S = half;
    }
    if (tid < CN) {
        unsigned long long kk = sk[255 - tid];
        g_start[b * CN + tid] = NPTS - 1 - (int)(unsigned)(kk & 0xFFFFFFFFull);
    }
}

// ---------------- kernel 3: persistent curve walk ----------------
struct SW {
    float  pv[WPB][KNBR][PVP];
    float  pre[WPB][C];
    float  cur[WPB][C];
    float  aw[2 * C];
    float  mw[4 * C];
    double red[WPB][4];
    float  bn[8];        // [0..3] momentum coefs, [4..5] agent coefs
};

__global__ void __launch_bounds__(WTPB, 1) k_walk(
    const int* __restrict__ idx,
    const float* __restrict__ agent_w,
    const float* __restrict__ agent_gp, const float* __restrict__ agent_bp,
    const float* __restrict__ mom_w,
    const float* __restrict__ mom_gp, const float* __restrict__ mom_bp,
    float* __restrict__ out)
{
    extern __shared__ char smraw[];
    SW* sm = (SW*)smraw;
    const unsigned F = 0xFFFFFFFFu;
    const int tid = threadIdx.x;
    const int w = tid >> 5;
    const int lane = tid & 31;

    for (int i = tid; i < 2 * C; i += WTPB) sm->aw[i] = agent_w[i];
    for (int i = tid; i < 4 * C; i += WTPB) sm->mw[i] = mom_w[i];
    __syncthreads();
    const float ag = agent_gp[0], ab = agent_bp[0];
    const float mg0 = mom_gp[0], mg1 = mom_gp[1], mb0 = mom_bp[0], mb1 = mom_bp[1];

    const int cid = blockIdx.x * WPB + w;
    const int b = cid >> 8;
    const int j = cid & 255;

    int fcur = b * NPTS + g_start[cid];
    float pre1 = g_xw[(size_t)fcur * C + lane];
    float pre2 = g_xw[(size_t)fcur * C + lane + 32];
    sm->pre[w][lane]      = pre1;
    sm->pre[w][lane + 32] = pre2;
    float cur1 = 0.f, cur2 = 0.f;
    __syncwarp();

    const int q  = lane & 7;
    const int rg = lane >> 3;

    for (int t = 0; t < CLEN; ++t) {
        const bool useD = (t > 0);

        // ==== PRE-POLL: gather + all dots that do NOT read blended pre ====
        int myg = b * NPTS + idx[(size_t)fcur * KNBR + lane];
        #pragma unroll
        for (int p = 0; p < 8; ++p) {
            int row = p * 4 + rg;
            int g = __shfl_sync(F, myg, row);
            const float4* src = (const float4*)&g_xw[(size_t)g * C];
            float4 v0 = src[q];
            float4 v1 = src[8 + q];
            *(float4*)&sm->pv[w][row][q * 4]      = v0;
            *(float4*)&sm->pv[w][row][32 + q * 4] = v1;
        }
        __syncwarp();   // pv stores visible within warp

        // per-k dots (lane owns neighbor `lane`): pvaw/dm0/dm1 + n2 (cur-only)
        float pvaw = 0.f, dm0 = 0.f, dm1 = 0.f, n2 = 0.f;
        #pragma unroll
        for (int cc = 0; cc < 16; ++cc) {
            float4 pvv = *(const float4*)&sm->pv[w][lane][cc * 4];
            float4 awv = *(const float4*)&sm->aw[cc * 4];
            float4 m0v = *(const float4*)&sm->mw[cc * 4];
            float4 m1v = *(const float4*)&sm->mw[128 + cc * 4];
            pvaw += pvv.x * awv.x; pvaw += pvv.y * awv.y;
            pvaw += pvv.z * awv.z; pvaw += pvv.w * awv.w;
            dm0 += pvv.x * m0v.x; dm0 += pvv.y * m0v.y;
            dm0 += pvv.z * m0v.z; dm0 += pvv.w * m0v.w;
            dm1 += pvv.x * m1v.x; dm1 += pvv.y * m1v.y;
            dm1 += pvv.z * m1v.z; dm1 += pvv.w * m1v.w;
            if (useD) {
                float4 cuv = *(const float4*)&sm->cur[w][cc * 4];
                float dx;
                dx = pvv.x - cuv.x; n2 += dx * dx;
                dx = pvv.y - cuv.y; n2 += dx * dx;
                dx = pvv.z - cuv.z; n2 += dx * dx;
                dx = pvv.w - cuv.w; n2 += dx * dx;
            }
        }

        // ==== momentum poll + serial tail (dotv half-loop only) ====
        float pd, pdot0, pdot1, dfac = 1.f;
        if (useD) {
            int slot = 2 * t - 1;
            if (tid == 0) {
                while (ldg_acq_s32(&g_rflag[slot][0]) == 0) { }
                sm->bn[0] = ldg_rlx_f32(&g_rcoef[slot][0]);
                sm->bn[1] = ldg_rlx_f32(&g_rcoef[slot][1]);
                sm->bn[2] = ldg_rlx_f32(&g_rcoef[slot][2]);
                sm->bn[3] = ldg_rlx_f32(&g_rcoef[slot][3]);
            }
            __syncthreads();
            float att = 0.f;
            if (lane < 2) {
                int f  = 2 * j + lane;
                int ch = f >> 8, jj = f & 255;
                float v0 = ldg_rlx_f32(&g_mm[b * 512 + jj])       * sm->bn[0] + sm->bn[1];
                float v1 = ldg_rlx_f32(&g_mm[b * 512 + 256 + jj]) * sm->bn[2] + sm->bn[3];
                float mx = fmaxf(v0, v1);
                float e0 = expf(v0 - mx), e1 = expf(v1 - mx);
                att = ((ch == 0) ? e0 : e1) / (e0 + e1);
            }
            float att0 = __shfl_sync(F, att, 0);
            float att1 = __shfl_sync(F, att, 1);
            pre1 = cur1 * att0 + pre1 * att1;
            pre2 = cur2 * att0 + pre2 * att1;
            sm->pre[w][lane]      = pre1;
            sm->pre[w][lane + 32] = pre2;
            __syncwarp();
            float pd_l = pre1 * sm->aw[C + lane]   + pre2 * sm->aw[C + lane + 32];
            float p0_l = pre1 * sm->mw[64 + lane]  + pre2 * sm->mw[96 + lane];
            float p1_l = pre1 * sm->mw[192 + lane] + pre2 * sm->mw[224 + lane];
            warpsum3(pd_l, p0_l, p1_l);
            pd = pd_l; pdot0 = p0_l; pdot1 = p1_l;
            float a1 = cur1 - pre1, a2 = cur2 - pre2;
            float anorm = sqrtf(warpsum(a1 * a1 + a2 * a2));
            // dotv half-loop: exact 657-bitstream expressions, blended pre from smem
            float dotv = 0.f;
            #pragma unroll
            for (int cc = 0; cc < 16; ++cc) {
                float4 pvv = *(const float4*)&sm->pv[w][lane][cc * 4];
                float4 cuv = *(const float4*)&sm->cur[w][cc * 4];
                float4 prv = *(const float4*)&sm->pre[w][cc * 4];
                float dx;
                dx = pvv.x - cuv.x; dotv += (cuv.x - prv.x) * dx;
                dx = pvv.y - cuv.y; dotv += (cuv.y - prv.y) * dx;
                dx = pvv.z - cuv.z; dotv += (cuv.z - prv.z) * dx;
                dx = pvv.w - cuv.w; dotv += (cuv.w - prv.w) * dx;
            }
            float div = fmaxf(anorm * sqrtf(n2), 1e-8f);
            dfac = fminf(fmaxf(1.f + dotv / div, 0.f), 1.f);
        } else {
            float pd_l = pre1 * sm->aw[C + lane]   + pre2 * sm->aw[C + lane + 32];
            float p0_l = pre1 * sm->mw[64 + lane]  + pre2 * sm->mw[96 + lane];
            float p1_l = pre1 * sm->mw[192 + lane] + pre2 * sm->mw[224 + lane];
            warpsum3(pd_l, p0_l, p1_l);
            pd = pd_l; pdot0 = p0_l; pdot1 = p1_l;
        }
        float raw = pvaw + pd;

        // ==== agent global BN: push-reduce into slot 2t ====
        {
            double ls = (double)raw;
            double l2 = (double)raw * (double)raw;
            warpsumd2(ls, l2);
            if (lane == 0) { sm->red[w][0] = ls; sm->red[w][1] = l2; }
            __syncthreads();
            int slot = 2 * t;
            if (w == 0) {
                double a  = (lane < WPB) ? sm->red[lane][0] : 0.0;
                double bb = (lane < WPB) ? sm->red[lane][1] : 0.0;
                warpsumd2(a, bb);
                if (lane < 2) {
                    double vv = (lane == 0) ? a * SCALE_S : bb * SCALE_Q;
                    long long L = __double2ll_rn(vv);
                    atomicAdd(&g_rsum[slot][lane][0], (unsigned long long)L);
                }
                __syncwarp();
                if (lane == 0) {
                    __threadfence();
                    unsigned int old = atomicAdd(&g_rcnt[slot][0], 1u);
                    if (old == WBLK - 1) {
                        __threadfence();
                        double S = (double)(long long)ldg_rlx_u64(&g_rsum[slot][0][0]) / SCALE_S;
                        double Q = (double)(long long)ldg_rlx_u64(&g_rsum[slot][1][0]) / SCALE_Q;
                        double mean = S / 65536.0, var = Q / 65536.0 - mean * mean;
                        float r = (float)(1.0 / sqrt(var + 1e-5));
                        stg_rlx_f32(&g_rcoef[slot][0], r * ag);
                        stg_rlx_f32(&g_rcoef[slot][1], ab - (float)mean * r * ag);
                        stg_rel_s32(&g_rflag[slot][0], 1);
                    }
                }
            }
            if (tid == 0) {
                while (ldg_acq_s32(&g_rflag[slot][0]) == 0) { }
                sm->bn[4] = ldg_rlx_f32(&g_rcoef[slot][0]);
                sm->bn[5] = ldg_rlx_f32(&g_rcoef[slot][1]);
            }
            __syncthreads();
        }

        // ==== straight-through select (argmax, first-index ties) ====
        float score = (raw * sm->bn[4] + sm->bn[5]) * dfac;
        float best = score; int bj = lane;
        #pragma unroll
        for (int o = 16; o; o >>= 1) {
            float os = __shfl_down_sync(F, best, o);
            int   oj = __shfl_down_sync(F, bj, o);
            if (os > best || (os == best && oj < bj)) { best = os; bj = oj; }
        }
        bj = __shfl_sync(F, bj, 0);
        int gsel = __shfl_sync(F, myg, bj);
        float c1 = sm->pv[w][bj][lane];
        float c2 = sm->pv[w][bj][32 + lane];
        cur1 = c1; cur2 = c2;
        sm->cur[w][lane]      = c1;
        sm->cur[w][lane + 32] = c2;
        g_curve[cid][t][lane]      = c1;
        g_curve[cid][t][lane + 32] = c2;
        fcur = gsel;
        __syncwarp();

        // ==== momentum arrival for step t+1 (slot 2t+1) ====
        if (t < CLEN - 1) {
            float m0 = __shfl_sync(F, dm0, bj) + pdot0;
            float m1 = __shfl_sync(F, dm1, bj) + pdot1;
            if (lane == 0) {
                g_mm[b * 512 + j]       = m0;
                g_mm[b * 512 + 256 + j] = m1;
                sm->red[w][0] = (double)m0; sm->red[w][1] = (double)m0 * m0;
                sm->red[w][2] = (double)m1; sm->red[w][3] = (double)m1 * m1;
            }
            __syncthreads();
            int slot = 2 * t + 1;
            if (w == 0) {
                double r0 = (lane < WPB) ? sm->red[lane][0] : 0.0;
                double r1 = (lane < WPB) ? sm->red[lane][1] : 0.0;
                double r2 = (lane < WPB) ? sm->red[lane][2] : 0.0;
                double r3 = (lane < WPB) ? sm->red[lane][3] : 0.0;
                warpsumd2(r0, r1); warpsumd2(r2, r3);
                if (lane < 4) {
                    double vv = (lane == 0) ? r0 * SCALE_S :
                                (lane == 1) ? r1 * SCALE_Q :
                                (lane == 2) ? r2 * SCALE_S : r3 * SCALE_Q;
                    long long L = __double2ll_rn(vv);
                    atomicAdd(&g_rsum[slot][lane][0], (unsigned long long)L);
                }
                __syncwarp();
                if (lane == 0) {
                    __threadfence();
                    unsigned int old = atomicAdd(&g_rcnt[slot][0], 1u);
                    if (old == WBLK - 1) {
                        __threadfence();
                        double S0 = (double)(long long)ldg_rlx_u64(&g_rsum[slot][0][0]) / SCALE_S;
                        double Q0 = (double)(long long)ldg_rlx_u64(&g_rsum[slot][1][0]) / SCALE_Q;
                        double S1 = (double)(long long)ldg_rlx_u64(&g_rsum[slot][2][0]) / SCALE_S;
                        double Q1 = (double)(long long)ldg_rlx_u64(&g_rsum[slot][3][0]) / SCALE_Q;
                        double mean0 = S0 / 2048.0, var0 = Q0 / 2048.0 - mean0 * mean0;
                        double mean1 = S1 / 2048.0, var1 = Q1 / 2048.0 - mean1 * mean1;
                        float r0f = (float)(1.0 / sqrt(var0 + 1e-5));
                        float r1f = (float)(1.0 / sqrt(var1 + 1e-5));
                        stg_rlx_f32(&g_rcoef[slot][0], r0f * mg0);
                        stg_rlx_f32(&g_rcoef[slot][1], mb0 - (float)mean0 * r0f * mg0);
                        stg_rlx_f32(&g_rcoef[slot][2], r1f * mg1);
                        stg_rlx_f32(&g_rcoef[slot][3], mb1 - (float)mean1 * r1f * mg1);
                        stg_rel_s32(&g_rflag[slot][0], 1);
                    }
                }
            }
        }
    }

    // ---- epilogue: per-warp transpose of the curve tile, fully coalesced out ----
    __syncwarp();
    {
        const float4* src = (const float4*)&g_curve[cid][lane][0];
        #pragma unroll
        for (int i = 0; i < 16; ++i) {
            float4 v = src[i];
            *(float4*)&sm->pv[w][lane][i * 4] = v;
        }
        __syncwarp();
        #pragma unroll
        for (int h = 0; h < 2; ++h) {
            int c = lane + h * 32;
            size_t obase = (((size_t)(b * C + c)) * CN + j) * CLEN;
            #pragma unroll
            for (int tc = 0; tc < 8; ++tc) {
                float4 v;
                v.x = sm->pv[w][tc * 4 + 0][c];
                v.y = sm->pv[w][tc * 4 + 1][c];
                v.z = sm->pv[w][tc * 4 + 2][c];
                v.w = sm->pv[w][tc * 4 + 3][c];
                *(float4*)&out[obase + tc * 4] = v;
            }
        }
    }
}

// ---------------- host ----------------
extern "C" void kernel_launch(void* const* d_in, const int* in_sizes, int n_in,
                              void* d_out, int out_size) {
    (void)in_sizes; (void)n_in; (void)out_size;
    const float* x       = (const float*)d_in[0];
    /* d_in[1] = xyz (unused by reference) */
    const int*   idx     = (const int*)d_in[2];
    const float* att_w   = (const float*)d_in[3];
    const float* agent_w = (const float*)d_in[4];
    const float* agent_g = (const float*)d_in[5];
    const float* agent_b = (const float*)d_in[6];
    const float* mom_w   = (const float*)d_in[7];
    const float* mom_g   = (const float*)d_in[8];
    const float* mom_b   = (const float*)d_in[9];
    float* out = (float*)d_out;

    cudaFuncSetAttribute(k_topk, cudaFuncAttributeMaxDynamicSharedMemorySize, NPTS * 8);
    cudaFuncSetAttribute(k_walk, cudaFuncAttributeMaxDynamicSharedMemorySize, (int)sizeof(SW));

    k_xw<<<BNB * 256, 256>>>(x, att_w);
    k_topk<<<BNB, 1024, NPTS * 8>>>();
    k_walk<<<WBLK, WTPB, sizeof(SW)>>>(idx, agent_w, agent_g, agent_b,
                                       mom_w, mom_g, mom_b, out);
}

// round 15
// speedup vs baseline: 1.8321x; 1.8321x over previous
#include <cuda_runtime.h>
#include <math.h>
#include <stdint.h>

#define BNB   8
#define C     64
#define NPTS  16384
#define KNBR  32
#define CN    256
#define CLEN  32
#define NCURVE (BNB*CN)     // 2048
#define WBLK  128           // walk grid blocks (co-resident on 148 SMs)
#define WTPB  512
#define WPB   16            // warps (=curves) per block
#define PVP   68            // padded pv row

#define SCALE_S 17179869184.0      // 2^34 for sums
#define SCALE_Q 1073741824.0       // 2^30 for sums of squares

// ---------------- device scratch (no allocations allowed) ----------------
__device__ float  g_xw[(size_t)BNB*NPTS*C];   // point-major gated features [bn*n][c]
__device__ float  g_paw[(size_t)BNB*NPTS];    // precomputed dot(xw[g], agent_w[0:64])
__device__ float  g_att[BNB*NPTS];
__device__ int    g_start[NCURVE];
__device__ float  g_mm[BNB*2*CN];             // raw momentum logits (scrambled softmax)
__device__ float  g_curve[NCURVE][CLEN][C];   // curve-major staging for output
// 64 reduction slots: agent(t)->slot 2t, momentum(t)->slot 2t-1
__device__ unsigned long long g_rsum[64][4][32];  // entry stride 256B
__device__ unsigned int       g_rcnt[64][32];     // arrival counter (one line)

// ---------------- helpers ----------------
__device__ __forceinline__ float warpsum(float v) {
    #pragma unroll
    for (int o = 16; o; o >>= 1) v += __shfl_down_sync(0xFFFFFFFFu, v, o);
    return __shfl_sync(0xFFFFFFFFu, v, 0);
}
__device__ __forceinline__ void warpsum2(float& a, float& b) {
    #pragma unroll
    for (int o = 16; o; o >>= 1) {
        a += __shfl_down_sync(0xFFFFFFFFu, a, o);
        b += __shfl_down_sync(0xFFFFFFFFu, b, o);
    }
    a = __shfl_sync(0xFFFFFFFFu, a, 0);
    b = __shfl_sync(0xFFFFFFFFu, b, 0);
}
__device__ __forceinline__ void warpsumd2(double& a, double& b) {
    #pragma unroll
    for (int o = 16; o; o >>= 1) {
        a += __shfl_down_sync(0xFFFFFFFFu, a, o);
        b += __shfl_down_sync(0xFFFFFFFFu, b, o);
    }
    a = __shfl_sync(0xFFFFFFFFu, a, 0);
    b = __shfl_sync(0xFFFFFFFFu, b, 0);
}
__device__ __forceinline__ int ldg_acq_s32(const unsigned int* p) {
    int v; asm volatile("ld.acquire.gpu.global.s32 %0, [%1];" : "=r"(v) : "l"(p) : "memory");
    return v;
}
__device__ __forceinline__ void red_release_add_u32(unsigned int* p, unsigned int v) {
    asm volatile("red.release.gpu.global.add.u32 [%0], %1;" :: "l"(p), "r"(v) : "memory");
}
__device__ __forceinline__ float ldg_rlx_f32(const float* p) {
    float v; asm volatile("ld.relaxed.gpu.global.f32 %0, [%1];" : "=f"(v) : "l"(p) : "memory");
    return v;
}
__device__ __forceinline__ unsigned long long ldg_rlx_u64(const unsigned long long* p) {
    unsigned long long v;
    asm volatile("ld.relaxed.gpu.global.u64 %0, [%1];" : "=l"(v) : "l"(p) : "memory");
    return v;
}

// ------- kernel 1: x_att + transposed gated features + paw + slot zeroing -------
__global__ void k_xw(const float* __restrict__ x, const float* __restrict__ att_w,
                     const float* __restrict__ agent_w) {
    __shared__ float sx[64][65];
    __shared__ float satt[64];
    __shared__ float sw[64];
    __shared__ float saw[64];
    const int tid = threadIdx.x;
    const int b  = blockIdx.x >> 8;
    const int n0 = (blockIdx.x & 255) * 64;
    if (blockIdx.x < 64) {           // reset reduction slots for this launch
        int s = blockIdx.x;
        if (tid < 4)       g_rsum[s][tid][0] = 0ull;
        else if (tid == 4) g_rcnt[s][0] = 0u;
    }
    if (tid < 64) { sw[tid] = att_w[tid]; saw[tid] = agent_w[tid]; }
    for (int i = tid; i < 64 * 64; i += 256) {
        int c = i >> 6, nn = i & 63;
        sx[c][nn] = x[((size_t)(b * C + c)) * NPTS + n0 + nn];
    }
    __syncthreads();
    if (tid < 64) {
        float s = 0.f;
        #pragma unroll
        for (int c = 0; c < 64; ++c) s += sx[c][tid] * sw[c];
        float a = 1.f / (1.f + expf(-s));
        satt[tid] = a;
        g_att[b * NPTS + n0 + tid] = a;
    }
    __syncthreads();
    for (int i = tid; i < 64 * 64; i += 256) {
        int nn = i >> 6, c = i & 63;
        g_xw[((size_t)(b * NPTS + n0 + nn)) * C + c] = sx[c][nn] * satt[nn];
    }
    // paw[n] = sum_c xw[n][c]*aw[c], channel order 0..63, FFMA chain (matches walk loop)
    if (tid < 64) {
        float a = satt[tid];
        float paw = 0.f;
        #pragma unroll
        for (int c = 0; c < 64; ++c) {
            float v = sx[c][tid] * a;      // identical rounding to stored g_xw value
            paw += v * saw[c];
        }
        g_paw[b * NPTS + n0 + tid] = paw;
    }
}

// -------- kernel 2: exact sorted top-256 per batch (chunk sort + max tournament) ----
__global__ void k_topk() {
    extern __shared__ unsigned long long sk[];
    const int tid = threadIdx.x;
    const int b = blockIdx.x;
    const int T = 1024;
    for (int i = tid; i < NPTS; i += T) {
        unsigned u = __float_as_uint(g_att[b * NPTS + i]);
        u = (u & 0x80000000u) ? ~u : (u | 0x80000000u);
        sk[i] = ((unsigned long long)u << 32) | (unsigned)(NPTS - 1 - i);
    }
    __syncthreads();
    for (int k = 2; k <= 256; k <<= 1) {
        for (int j = k >> 1; j > 0; j >>= 1) {
            for (int i = tid; i < NPTS; i += T) {
                int ixj = i ^ j;
                if (ixj > i) {
                    bool up = ((i & k) == 0);
                    unsigned long long a = sk[i], c = sk[ixj];
                    if ((a > c) == up) { sk[i] = c; sk[ixj] = a; }
                }
            }
            __syncthreads();
        }
    }
    int S = NPTS;
    while (S > 256) {
        int half = S >> 1;
        unsigned long long v[8];
        int cnt = 0;
        for (int i = tid; i < half; i += T) {
            int p = i >> 8, o = i & 255;
            unsigned long long a = sk[(2 * p) * 256 + o];
            unsigned long long c = sk[(2 * p + 1) * 256 + o];
            v[cnt++] = a > c ? a : c;
        }
        __syncthreads();
        cnt = 0;
        for (int i = tid; i < half; i += T) sk[i] = v[cnt++];
        __syncthreads();
        for (int j = 128; j > 0; j >>= 1) {
            for (int i = tid; i < half; i += T) {
                int ixj = i ^ j;
                if (ixj > i) {
                    bool up = ((i & 256) == 0);
                    unsigned long long a = sk[i], c = sk[ixj];
                    if ((a > c) == up) { sk[i] = c; sk[ixj] = a; }
                }
            }
            __syncthreads();
        }
        S = half;
    }
    if (tid < CN) {
        unsigned long long kk = sk[255 - tid];
        g_start[b * CN + tid] = NPTS - 1 - (int)(unsigned)(kk & 0xFFFFFFFFull);
    }
}

// ---------------- kernel 3: persistent curve walk ----------------
struct SW {
    float  pv[WPB][KNBR][PVP];
    float  pre[WPB][C];
    float  cur[WPB][C];
    float  aw[2 * C];
    float  mw[4 * C];
    double red[WPB][4];
    float  bn[8];        // [0..3] momentum coefs, [4..5] agent coefs
};

__global__ void __launch_bounds__(WTPB, 1) k_walk(
    const int* __restrict__ idx,
    const float* __restrict__ agent_w,
    const float* __restrict__ agent_gp, const float* __restrict__ agent_bp,
    const float* __restrict__ mom_w,
    const float* __restrict__ mom_gp, const float* __restrict__ mom_bp,
    float* __restrict__ out)
{
    extern __shared__ char smraw[];
    SW* sm = (SW*)smraw;
    const unsigned F = 0xFFFFFFFFu;
    const int tid = threadIdx.x;
    const int w = tid >> 5;
    const int lane = tid & 31;

    for (int i = tid; i < 2 * C; i += WTPB) sm->aw[i] = agent_w[i];
    for (int i = tid; i < 4 * C; i += WTPB) sm->mw[i] = mom_w[i];
    __syncthreads();
    const float ag = agent_gp[0], ab = agent_bp[0];
    const float mg0 = mom_gp[0], mg1 = mom_gp[1], mb0 = mom_bp[0], mb1 = mom_bp[1];

    const int cid = blockIdx.x * WPB + w;
    const int b = cid >> 8;
    const int j = cid & 255;

    int fcur = b * NPTS + g_start[cid];
    float pre1 = g_xw[(size_t)fcur * C + lane];
    float pre2 = g_xw[(size_t)fcur * C + lane + 32];
    sm->pre[w][lane]      = pre1;
    sm->pre[w][lane + 32] = pre2;
    float cur1 = 0.f, cur2 = 0.f;

    const int q  = lane & 7;
    const int rg = lane >> 3;

    // ---- preamble gather for t=0 ----
    int myg = b * NPTS + idx[(size_t)fcur * KNBR + lane];
    float mypaw = g_paw[myg];
    #pragma unroll
    for (int p = 0; p < 8; ++p) {
        int row = p * 4 + rg;
        int g = __shfl_sync(F, myg, row);
        const float4* src = (const float4*)&g_xw[(size_t)g * C];
        float4 v0 = src[q];
        float4 v1 = src[8 + q];
        *(float4*)&sm->pv[w][row][q * 4]      = v0;
        *(float4*)&sm->pv[w][row][32 + q * 4] = v1;
    }
    __syncwarp();

    for (int t = 0; t < CLEN; ++t) {
        const bool useD = (t > 0);

        float pd, dfac = 1.f;
        if (useD) {
            // ---- poll momentum counter; every block computes coefs locally ----
            int slot = 2 * t - 1;
            if (tid == 0) {
                while (ldg_acq_s32(&g_rcnt[slot][0]) < WBLK) { }
                double S0 = (double)(long long)ldg_rlx_u64(&g_rsum[slot][0][0]) / SCALE_S;
                double Q0 = (double)(long long)ldg_rlx_u64(&g_rsum[slot][1][0]) / SCALE_Q;
                double S1 = (double)(long long)ldg_rlx_u64(&g_rsum[slot][2][0]) / SCALE_S;
                double Q1 = (double)(long long)ldg_rlx_u64(&g_rsum[slot][3][0]) / SCALE_Q;
                double mean0 = S0 / 2048.0, var0 = Q0 / 2048.0 - mean0 * mean0;
                double mean1 = S1 / 2048.0, var1 = Q1 / 2048.0 - mean1 * mean1;
                float r0f = (float)(1.0 / sqrt(var0 + 1e-5));
                float r1f = (float)(1.0 / sqrt(var1 + 1e-5));
                sm->bn[0] = r0f * mg0; sm->bn[1] = mb0 - (float)mean0 * r0f * mg0;
                sm->bn[2] = r1f * mg1; sm->bn[3] = mb1 - (float)mean1 * r1f * mg1;
            }
            __syncthreads();
            // scrambled attention weights (torch .view reshape semantics)
            float att = 0.f;
            if (lane < 2) {
                int f  = 2 * j + lane;
                int ch = f >> 8, jj = f & 255;
                float v0 = ldg_rlx_f32(&g_mm[b * 512 + jj])       * sm->bn[0] + sm->bn[1];
                float v1 = ldg_rlx_f32(&g_mm[b * 512 + 256 + jj]) * sm->bn[2] + sm->bn[3];
                float mx = fmaxf(v0, v1);
                float e0 = expf(v0 - mx), e1 = expf(v1 - mx);
                att = ((ch == 0) ? e0 : e1) / (e0 + e1);
            }
            float att0 = __shfl_sync(F, att, 0);
            float att1 = __shfl_sync(F, att, 1);
            pre1 = cur1 * att0 + pre1 * att1;
            pre2 = cur2 * att0 + pre2 * att1;
            sm->pre[w][lane]      = pre1;
            sm->pre[w][lane + 32] = pre2;
            __syncwarp();
            pd = warpsum(pre1 * sm->aw[C + lane] + pre2 * sm->aw[C + lane + 32]);
            float a1 = cur1 - pre1, a2 = cur2 - pre2;
            float anorm = sqrtf(warpsum(a1 * a1 + a2 * a2));
            __syncwarp();
            // crossover loop (lane owns neighbor `lane`): exact 657 expressions
            float dotv = 0.f, n2 = 0.f;
            #pragma unroll
            for (int cc = 0; cc < 16; ++cc) {
                float4 pvv = *(const float4*)&sm->pv[w][lane][cc * 4];
                float4 cuv = *(const float4*)&sm->cur[w][cc * 4];
                float4 prv = *(const float4*)&sm->pre[w][cc * 4];
                float dx;
                dx = pvv.x - cuv.x; dotv += (cuv.x - prv.x) * dx; n2 += dx * dx;
                dx = pvv.y - cuv.y; dotv += (cuv.y - prv.y) * dx; n2 += dx * dx;
                dx = pvv.z - cuv.z; dotv += (cuv.z - prv.z) * dx; n2 += dx * dx;
                dx = pvv.w - cuv.w; dotv += (cuv.w - prv.w) * dx; n2 += dx * dx;
            }
            float div = fmaxf(anorm * sqrtf(n2), 1e-8f);
            dfac = fminf(fmaxf(1.f + dotv / div, 0.f), 1.f);
        } else {
            pd = warpsum(pre1 * sm->aw[C + lane] + pre2 * sm->aw[C + lane + 32]);
        }
        float raw = mypaw + pd;

        // ==== agent global BN: push integer partials into slot 2t ====
        {
            double ls = (double)raw;
            double l2 = (double)raw * (double)raw;
            warpsumd2(ls, l2);
            if (lane == 0) { sm->red[w][0] = ls; sm->red[w][1] = l2; }
            __syncthreads();
            int slot = 2 * t;
            if (w == 0) {
                double a  = (lane < WPB) ? sm->red[lane][0] : 0.0;
                double bb = (lane < WPB) ? sm->red[lane][1] : 0.0;
                warpsumd2(a, bb);
                if (lane == 0) {
                    long long L0 = __double2ll_rn(a * SCALE_S);
                    long long L1 = __double2ll_rn(bb * SCALE_Q);
                    atomicAdd(&g_rsum[slot][0][0], (unsigned long long)L0);
                    atomicAdd(&g_rsum[slot][1][0], (unsigned long long)L1);
                    __threadfence();
                    red_release_add_u32(&g_rcnt[slot][0], 1u);
                }
            }
            if (tid == 0) {
                while (ldg_acq_s32(&g_rcnt[slot][0]) < WBLK) { }
                double S = (double)(long long)ldg_rlx_u64(&g_rsum[slot][0][0]) / SCALE_S;
                double Q = (double)(long long)ldg_rlx_u64(&g_rsum[slot][1][0]) / SCALE_Q;
                double mean = S / 65536.0, var = Q / 65536.0 - mean * mean;
                float r = (float)(1.0 / sqrt(var + 1e-5));
                sm->bn[4] = r * ag;
                sm->bn[5] = ab - (float)mean * r * ag;
            }
            __syncthreads();
        }

        // ==== straight-through select (argmax, first-index ties) ====
        float score = (raw * sm->bn[4] + sm->bn[5]) * dfac;
        float best = score; int bj = lane;
        #pragma unroll
        for (int o = 16; o; o >>= 1) {
            float os = __shfl_down_sync(F, best, o);
            int   oj = __shfl_down_sync(F, bj, o);
            if (os > best || (os == best && oj < bj)) { best = os; bj = oj; }
        }
        bj = __shfl_sync(F, bj, 0);
        int gsel = __shfl_sync(F, myg, bj);
        float c1 = sm->pv[w][bj][lane];
        float c2 = sm->pv[w][bj][32 + lane];
        cur1 = c1; cur2 = c2;
        sm->cur[w][lane]      = c1;
        sm->cur[w][lane + 32] = c2;
        g_curve[cid][t][lane]      = c1;
        g_curve[cid][t][lane + 32] = c2;
        __syncwarp();

        if (t < CLEN - 1) {
            // prefetch next idx row early (overlaps momentum reduce below)
            int nidx = idx[(size_t)gsel * KNBR + lane];

            // ==== momentum logits (R5 form) + push into slot 2t+1 ====
            float m0 = cur1 * sm->mw[lane]       + cur2 * sm->mw[32 + lane]
                     + pre1 * sm->mw[64 + lane]  + pre2 * sm->mw[96 + lane];
            float m1 = cur1 * sm->mw[128 + lane] + cur2 * sm->mw[160 + lane]
                     + pre1 * sm->mw[192 + lane] + pre2 * sm->mw[224 + lane];
            warpsum2(m0, m1);
            if (lane == 0) {
                g_mm[b * 512 + j]       = m0;
                g_mm[b * 512 + 256 + j] = m1;
                sm->red[w][0] = (double)m0; sm->red[w][1] = (double)m0 * m0;
                sm->red[w][2] = (double)m1; sm->red[w][3] = (double)m1 * m1;
            }
            __syncthreads();
            int slot = 2 * t + 1;
            if (w == 0) {
                double r0 = (lane < WPB) ? sm->red[lane][0] : 0.0;
                double r1 = (lane < WPB) ? sm->red[lane][1] : 0.0;
                double r2 = (lane < WPB) ? sm->red[lane][2] : 0.0;
                double r3 = (lane < WPB) ? sm->red[lane][3] : 0.0;
                warpsumd2(r0, r1); warpsumd2(r2, r3);
                if (lane == 0) {
                    long long L0 = __double2ll_rn(r0 * SCALE_S);
                    long long L1 = __double2ll_rn(r1 * SCALE_Q);
                    long long L2 = __double2ll_rn(r2 * SCALE_S);
                    long long L3 = __double2ll_rn(r3 * SCALE_Q);
                    atomicAdd(&g_rsum[slot][0][0], (unsigned long long)L0);
                    atomicAdd(&g_rsum[slot][1][0], (unsigned long long)L1);
                    atomicAdd(&g_rsum[slot][2][0], (unsigned long long)L2);
                    atomicAdd(&g_rsum[slot][3][0], (unsigned long long)L3);
                    __threadfence();
                    red_release_add_u32(&g_rcnt[slot][0], 1u);
                }
            }

            // ==== gather next step's neighbor rows (overlaps momentum reduce) ====
            myg = b * NPTS + nidx;
            mypaw = g_paw[myg];
            #pragma unroll
            for (int p = 0; p < 8; ++p) {
                int row = p * 4 + rg;
                int g = __shfl_sync(F, myg, row);
                const float4* src = (const float4*)&g_xw[(size_t)g * C];
                float4 v0 = src[q];
                float4 v1 = src[8 + q];
                *(float4*)&sm->pv[w][row][q * 4]      = v0;
                *(float4*)&sm->pv[w][row][32 + q * 4] = v1;
            }
            __syncwarp();
        }
    }

    // ---- epilogue: per-warp transpose of the curve tile, fully coalesced out ----
    __syncwarp();
    {
        const float4* src = (const float4*)&g_curve[cid][lane][0];
        #pragma unroll
        for (int i = 0; i < 16; ++i) {
            float4 v = src[i];
            *(float4*)&sm->pv[w][lane][i * 4] = v;
        }
        __syncwarp();
        #pragma unroll
        for (int h = 0; h < 2; ++h) {
            int c = lane + h * 32;
            size_t obase = (((size_t)(b * C + c)) * CN + j) * CLEN;
            #pragma unroll
            for (int tc = 0; tc < 8; ++tc) {
                float4 v;
                v.x = sm->pv[w][tc * 4 + 0][c];
                v.y = sm->pv[w][tc * 4 + 1][c];
                v.z = sm->pv[w][tc * 4 + 2][c];
                v.w = sm->pv[w][tc * 4 + 3][c];
                *(float4*)&out[obase + tc * 4] = v;
            }
        }
    }
}

// ---------------- host ----------------
extern "C" void kernel_launch(void* const* d_in, const int* in_sizes, int n_in,
                              void* d_out, int out_size) {
    (void)in_sizes; (void)n_in; (void)out_size;
    const float* x       = (const float*)d_in[0];
    /* d_in[1] = xyz (unused by reference) */
    const int*   idx     = (const int*)d_in[2];
    const float* att_w   = (const float*)d_in[3];
    const float* agent_w = (const float*)d_in[4];
    const float* agent_g = (const float*)d_in[5];
    const float* agent_b = (const float*)d_in[6];
    const float* mom_w   = (const float*)d_in[7];
    const float* mom_g   = (const float*)d_in[8];
    const float* mom_b   = (const float*)d_in[9];
    float* out = (float*)d_out;

    cudaFuncSetAttribute(k_topk, cudaFuncAttributeMaxDynamicSharedMemorySize, NPTS * 8);
    cudaFuncSetAttribute(k_walk, cudaFuncAttributeMaxDynamicSharedMemorySize, (int)sizeof(SW));

    k_xw<<<BNB * 256, 256>>>(x, att_w, agent_w);
    k_topk<<<BNB, 1024, NPTS * 8>>>();
    k_walk<<<WBLK, WTPB, sizeof(SW)>>>(idx, agent_w, agent_g, agent_b,
                                       mom_w, mom_g, mom_b, out);
}

// round 16
// speedup vs baseline: 1.8681x; 1.0197x over previous
#include <cuda_runtime.h>
#include <math.h>
#include <stdint.h>

#define BNB   8
#define C     64
#define NPTS  16384
#define KNBR  32
#define CN    256
#define CLEN  32
#define NCURVE (BNB*CN)     // 2048
#define WBLK  128           // walk grid blocks (co-resident on 148 SMs)
#define WTPB  512
#define WPB   16            // warps (=curves) per block
#define PVP   68            // padded pv row

#define SCALE_S 17179869184.0      // 2^34 for sums
#define SCALE_Q 1073741824.0       // 2^30 for sums of squares

// ---------------- device scratch (no allocations allowed) ----------------
__device__ float  g_xw[(size_t)BNB*NPTS*C];   // point-major gated features [bn*n][c]
__device__ float  g_paw[(size_t)BNB*NPTS];    // precomputed dot(xw[g], agent_w[0:64])
__device__ float  g_att[BNB*NPTS];
__device__ int    g_start[NCURVE];
__device__ float  g_mm[BNB*2*CN];             // raw momentum logits (scrambled softmax)
__device__ float  g_curve[NCURVE][CLEN][C];   // curve-major staging for output
// 64 reduction slots: agent(t)->slot 2t, momentum(t)->slot 2t+1
__device__ unsigned long long g_rsum[64][4][32];  // entry stride 256B
__device__ unsigned int       g_rcnt[64][32];     // arrival counter (one line)

// ---------------- helpers ----------------
__device__ __forceinline__ float warpsum(float v) {
    #pragma unroll
    for (int o = 16; o; o >>= 1) v += __shfl_down_sync(0xFFFFFFFFu, v, o);
    return __shfl_sync(0xFFFFFFFFu, v, 0);
}
__device__ __forceinline__ void warpsum3(float& a, float& b, float& c) {
    #pragma unroll
    for (int o = 16; o; o >>= 1) {
        a += __shfl_down_sync(0xFFFFFFFFu, a, o);
        b += __shfl_down_sync(0xFFFFFFFFu, b, o);
        c += __shfl_down_sync(0xFFFFFFFFu, c, o);
    }
    a = __shfl_sync(0xFFFFFFFFu, a, 0);
    b = __shfl_sync(0xFFFFFFFFu, b, 0);
    c = __shfl_sync(0xFFFFFFFFu, c, 0);
}
__device__ __forceinline__ void warpsumd2(double& a, double& b) {
    #pragma unroll
    for (int o = 16; o; o >>= 1) {
        a += __shfl_down_sync(0xFFFFFFFFu, a, o);
        b += __shfl_down_sync(0xFFFFFFFFu, b, o);
    }
    a = __shfl_sync(0xFFFFFFFFu, a, 0);
    b = __shfl_sync(0xFFFFFFFFu, b, 0);
}
__device__ __forceinline__ int ldg_acq_s32(const unsigned int* p) {
    int v; asm volatile("ld.acquire.gpu.global.s32 %0, [%1];" : "=r"(v) : "l"(p) : "memory");
    return v;
}
__device__ __forceinline__ void red_release_add_u32(unsigned int* p, unsigned int v) {
    asm volatile("red.release.gpu.global.add.u32 [%0], %1;" :: "l"(p), "r"(v) : "memory");
}
__device__ __forceinline__ float ldg_rlx_f32(const float* p) {
    float v; asm volatile("ld.relaxed.gpu.global.f32 %0, [%1];" : "=f"(v) : "l"(p) : "memory");
    return v;
}
__device__ __forceinline__ unsigned long long ldg_rlx_u64(const unsigned long long* p) {
    unsigned long long v;
    asm volatile("ld.relaxed.gpu.global.u64 %0, [%1];" : "=l"(v) : "l"(p) : "memory");
    return v;
}
__device__ __forceinline__ void sts_rel_s32(int* p, int v) {
    asm volatile("st.release.cta.s32 [%0], %1;" :: "l"(p), "r"(v) : "memory");
}
__device__ __forceinline__ int lds_acq_s32(const int* p) {
    int v; asm volatile("ld.acquire.cta.s32 %0, [%1];" : "=r"(v) : "l"(p) : "memory");
    return v;
}
#define BAR_ARRIVE(id) asm volatile("bar.arrive %0, %1;" :: "n"(id), "n"(WTPB) : "memory")
#define BAR_SYNC(id)   asm volatile("bar.sync %0, %1;"   :: "n"(id), "n"(WTPB) : "memory")

// ------- kernel 1: x_att + transposed gated features + paw + slot zeroing -------
__global__ void k_xw(const float* __restrict__ x, const float* __restrict__ att_w,
                     const float* __restrict__ agent_w) {
    __shared__ float sx[64][65];
    __shared__ float satt[64];
    __shared__ float sw[64];
    __shared__ float saw[64];
    const int tid = threadIdx.x;
    const int b  = blockIdx.x >> 8;
    const int n0 = (blockIdx.x & 255) * 64;
    if (blockIdx.x < 64) {           // reset reduction slots for this launch
        int s = blockIdx.x;
        if (tid < 4)       g_rsum[s][tid][0] = 0ull;
        else if (tid == 4) g_rcnt[s][0] = 0u;
    }
    if (tid < 64) { sw[tid] = att_w[tid]; saw[tid] = agent_w[tid]; }
    for (int i = tid; i < 64 * 64; i += 256) {
        int c = i >> 6, nn = i & 63;
        sx[c][nn] = x[((size_t)(b * C + c)) * NPTS + n0 + nn];
    }
    __syncthreads();
    if (tid < 64) {
        float s = 0.f;
        #pragma unroll
        for (int c = 0; c < 64; ++c) s += sx[c][tid] * sw[c];
        float a = 1.f / (1.f + expf(-s));
        satt[tid] = a;
        g_att[b * NPTS + n0 + tid] = a;
    }
    __syncthreads();
    for (int i = tid; i < 64 * 64; i += 256) {
        int nn = i >> 6, c = i & 63;
        g_xw[((size_t)(b * NPTS + n0 + nn)) * C + c] = sx[c][nn] * satt[nn];
    }
    if (tid < 64) {
        float a = satt[tid];
        float paw = 0.f;
        #pragma unroll
        for (int c = 0; c < 64; ++c) {
            float v = sx[c][tid] * a;
            paw += v * saw[c];
        }
        g_paw[b * NPTS + n0 + tid] = paw;
    }
}

// -------- kernel 2: exact sorted top-256 per batch (chunk sort + max tournament) ----
__global__ void k_topk() {
    extern __shared__ unsigned long long sk[];
    const int tid = threadIdx.x;
    const int b = blockIdx.x;
    const int T = 1024;
    for (int i = tid; i < NPTS; i += T) {
        unsigned u = __float_as_uint(g_att[b * NPTS + i]);
        u = (u & 0x80000000u) ? ~u : (u | 0x80000000u);
        sk[i] = ((unsigned long long)u << 32) | (unsigned)(NPTS - 1 - i);
    }
    __syncthreads();
    for (int k = 2; k <= 256; k <<= 1) {
        for (int j = k >> 1; j > 0; j >>= 1) {
            for (int i = tid; i < NPTS; i += T) {
                int ixj = i ^ j;
                if (ixj > i) {
                    bool up = ((i & k) == 0);
                    unsigned long long a = sk[i], c = sk[ixj];
                    if ((a > c) == up) { sk[i] = c; sk[ixj] = a; }
                }
            }
            __syncthreads();
        }
    }
    int S = NPTS;
    while (S > 256) {
        int half = S >> 1;
        unsigned long long v[8];
        int cnt = 0;
        for (int i = tid; i < half; i += T) {
            int p = i >> 8, o = i & 255;
            unsigned long long a = sk[(2 * p) * 256 + o];
            unsigned long long c = sk[(2 * p + 1) * 256 + o];
            v[cnt++] = a > c ? a : c;
        }
        __syncthreads();
        cnt = 0;
        for (int i = tid; i < half; i += T) sk[i] = v[cnt++];
        __syncthreads();
        for (int j = 128; j > 0; j >>= 1) {
            for (int i = tid; i < half; i += T) {
                int ixj = i ^ j;
                if (ixj > i) {
                    bool up = ((i & 256) == 0);
                    unsigned long long a = sk[i], c = sk[ixj];
                    if ((a > c) == up) { sk[i] = c; sk[ixj] = a; }
                }
            }
            __syncthreads();
        }
        S = half;
    }
    if (tid < CN) {
        unsigned long long kk = sk[255 - tid];
        g_start[b * CN + tid] = NPTS - 1 - (int)(unsigned)(kk & 0xFFFFFFFFull);
    }
}

// ---------------- kernel 3: persistent curve walk (warp-decoupled) ----------------
struct SW {
    float  pv[WPB][KNBR][PVP];
    float  pre[WPB][C];
    float  cur[WPB][C];
    float  aw[2 * C];
    float  mw[4 * C];
    double red_a[WPB][2];
    double red_m[WPB][4];
    float  bnm[4];        // momentum coefs (published by w0)
    float  bna[2];        // agent coefs (published by w0)
    int    flagM;
    int    flagA;
};

__global__ void __launch_bounds__(WTPB, 1) k_walk(
    const int* __restrict__ idx,
    const float* __restrict__ agent_w,
    const float* __restrict__ agent_gp, const float* __restrict__ agent_bp,
    const float* __restrict__ mom_w,
    const float* __restrict__ mom_gp, const float* __restrict__ mom_bp,
    float* __restrict__ out)
{
    extern __shared__ char smraw[];
    SW* sm = (SW*)smraw;
    const unsigned F = 0xFFFFFFFFu;
    const int tid = threadIdx.x;
    const int w = tid >> 5;
    const int lane = tid & 31;

    for (int i = tid; i < 2 * C; i += WTPB) sm->aw[i] = agent_w[i];
    for (int i = tid; i < 4 * C; i += WTPB) sm->mw[i] = mom_w[i];
    if (tid == 0) { sm->flagM = -1; sm->flagA = -1; }
    __syncthreads();
    const float ag = agent_gp[0], ab = agent_bp[0];
    const float mg0 = mom_gp[0], mg1 = mom_gp[1], mb0 = mom_bp[0], mb1 = mom_bp[1];

    const int cid = blockIdx.x * WPB + w;
    const int b = cid >> 8;
    const int j = cid & 255;

    int fcur = b * NPTS + g_start[cid];
    float pre1 = g_xw[(size_t)fcur * C + lane];
    float pre2 = g_xw[(size_t)fcur * C + lane + 32];
    sm->pre[w][lane]      = pre1;
    sm->pre[w][lane + 32] = pre2;
    float cur1 = 0.f, cur2 = 0.f;

    const int q  = lane & 7;
    const int rg = lane >> 3;

    // ---- preamble gather for t=0 ----
    int myg = b * NPTS + idx[(size_t)fcur * KNBR + lane];
    float mypaw = g_paw[myg];
    #pragma unroll
    for (int p = 0; p < 8; ++p) {
        int row = p * 4 + rg;
        int g = __shfl_sync(F, myg, row);
        const float4* src = (const float4*)&g_xw[(size_t)g * C];
        float4 v0 = src[q];
        float4 v1 = src[8 + q];
        *(float4*)&sm->pv[w][row][q * 4]      = v0;
        *(float4*)&sm->pv[w][row][32 + q * 4] = v1;
    }
    __syncwarp();

    for (int t = 0; t < CLEN; ++t) {
        const bool useD = (t > 0);

        // ---- pre-poll: per-k momentum dots (overlap momentum reduce RT) ----
        float dm0 = 0.f, dm1 = 0.f;
        if (t < CLEN - 1) {
            #pragma unroll
            for (int cc = 0; cc < 16; ++cc) {
                float4 pvv = *(const float4*)&sm->pv[w][lane][cc * 4];
                float4 m0v = *(const float4*)&sm->mw[cc * 4];
                float4 m1v = *(const float4*)&sm->mw[128 + cc * 4];
                dm0 += pvv.x * m0v.x; dm0 += pvv.y * m0v.y;
                dm0 += pvv.z * m0v.z; dm0 += pvv.w * m0v.w;
                dm1 += pvv.x * m1v.x; dm1 += pvv.y * m1v.y;
                dm1 += pvv.z * m1v.z; dm1 += pvv.w * m1v.w;
            }
        }

        float pd, pdot0, pdot1, dfac = 1.f;
        if (useD) {
            // ---- momentum coefs: w0 polls + publishes; warps spin on smem flag ----
            int slot = 2 * t - 1;
            if (w == 0) {
                while (ldg_acq_s32(&g_rcnt[slot][0]) < WBLK) { }
                if (lane == 0) {
                    double S0 = (double)(long long)ldg_rlx_u64(&g_rsum[slot][0][0]) / SCALE_S;
                    double Q0 = (double)(long long)ldg_rlx_u64(&g_rsum[slot][1][0]) / SCALE_Q;
                    double S1 = (double)(long long)ldg_rlx_u64(&g_rsum[slot][2][0]) / SCALE_S;
                    double Q1 = (double)(long long)ldg_rlx_u64(&g_rsum[slot][3][0]) / SCALE_Q;
                    double mean0 = S0 / 2048.0, var0 = Q0 / 2048.0 - mean0 * mean0;
                    double mean1 = S1 / 2048.0, var1 = Q1 / 2048.0 - mean1 * mean1;
                    float r0f = (float)(1.0 / sqrt(var0 + 1e-5));
                    float r1f = (float)(1.0 / sqrt(var1 + 1e-5));
                    sm->bnm[0] = r0f * mg0; sm->bnm[1] = mb0 - (float)mean0 * r0f * mg0;
                    sm->bnm[2] = r1f * mg1; sm->bnm[3] = mb1 - (float)mean1 * r1f * mg1;
                    sts_rel_s32(&sm->flagM, t);
                }
            }
            while (lds_acq_s32(&sm->flagM) != t) { }
            float c0m = sm->bnm[0], c0b = sm->bnm[1], c1m = sm->bnm[2], c1b = sm->bnm[3];
            // scrambled attention weights (torch .view reshape semantics)
            float att = 0.f;
            if (lane < 2) {
                int f  = 2 * j + lane;
                int ch = f >> 8, jj = f & 255;
                float v0 = ldg_rlx_f32(&g_mm[b * 512 + jj])       * c0m + c0b;
                float v1 = ldg_rlx_f32(&g_mm[b * 512 + 256 + jj]) * c1m + c1b;
                float mx = fmaxf(v0, v1);
                float e0 = expf(v0 - mx), e1 = expf(v1 - mx);
                att = ((ch == 0) ? e0 : e1) / (e0 + e1);
            }
            float att0 = __shfl_sync(F, att, 0);
            float att1 = __shfl_sync(F, att, 1);
            pre1 = cur1 * att0 + pre1 * att1;
            pre2 = cur2 * att0 + pre2 * att1;
            sm->pre[w][lane]      = pre1;
            sm->pre[w][lane + 32] = pre2;
            __syncwarp();
        }
        {
            float pd_l = pre1 * sm->aw[C + lane]   + pre2 * sm->aw[C + lane + 32];
            float p0_l = pre1 * sm->mw[64 + lane]  + pre2 * sm->mw[96 + lane];
            float p1_l = pre1 * sm->mw[192 + lane] + pre2 * sm->mw[224 + lane];
            warpsum3(pd_l, p0_l, p1_l);
            pd = pd_l; pdot0 = p0_l; pdot1 = p1_l;
        }
        float raw = mypaw + pd;

        // ---- agent push: partial to smem, arrive; w0 aggregates + pushes ----
        {
            double ls = (double)raw;
            double l2 = (double)raw * (double)raw;
            warpsumd2(ls, l2);
            if (lane == 0) { sm->red_a[w][0] = ls; sm->red_a[w][1] = l2; }
            int slot = 2 * t;
            if (w == 0) {
                BAR_SYNC(1);
                double a  = (lane < WPB) ? sm->red_a[lane][0] : 0.0;
                double bb = (lane < WPB) ? sm->red_a[lane][1] : 0.0;
                warpsumd2(a, bb);
                if (lane == 0) {
                    long long L0 = __double2ll_rn(a * SCALE_S);
                    long long L1 = __double2ll_rn(bb * SCALE_Q);
                    atomicAdd(&g_rsum[slot][0][0], (unsigned long long)L0);
                    atomicAdd(&g_rsum[slot][1][0], (unsigned long long)L1);
                    __threadfence();
                    red_release_add_u32(&g_rcnt[slot][0], 1u);
                }
            } else {
                BAR_ARRIVE(1);
            }
        }

        // ---- crossover + dfac: overlaps agent reduce round-trip ----
        if (useD) {
            float a1 = cur1 - pre1, a2 = cur2 - pre2;
            float anorm = sqrtf(warpsum(a1 * a1 + a2 * a2));
            float dotv = 0.f, n2 = 0.f;
            #pragma unroll
            for (int cc = 0; cc < 16; ++cc) {
                float4 pvv = *(const float4*)&sm->pv[w][lane][cc * 4];
                float4 cuv = *(const float4*)&sm->cur[w][cc * 4];
                float4 prv = *(const float4*)&sm->pre[w][cc * 4];
                float dx;
                dx = pvv.x - cuv.x; dotv += (cuv.x - prv.x) * dx; n2 += dx * dx;
                dx = pvv.y - cuv.y; dotv += (cuv.y - prv.y) * dx; n2 += dx * dx;
                dx = pvv.z - cuv.z; dotv += (cuv.z - prv.z) * dx; n2 += dx * dx;
                dx = pvv.w - cuv.w; dotv += (cuv.w - prv.w) * dx; n2 += dx * dx;
            }
            float div = fmaxf(anorm * sqrtf(n2), 1e-8f);
            dfac = fminf(fmaxf(1.f + dotv / div, 0.f), 1.f);
        }

        // ---- agent coefs: w0 polls + publishes; warps spin on smem flag ----
        {
            int slot = 2 * t;
            if (w == 0) {
                while (ldg_acq_s32(&g_rcnt[slot][0]) < WBLK) { }
                if (lane == 0) {
                    double S = (double)(long long)ldg_rlx_u64(&g_rsum[slot][0][0]) / SCALE_S;
                    double Q = (double)(long long)ldg_rlx_u64(&g_rsum[slot][1][0]) / SCALE_Q;
                    double mean = S / 65536.0, var = Q / 65536.0 - mean * mean;
                    float r = (float)(1.0 / sqrt(var + 1e-5));
                    sm->bna[0] = r * ag;
                    sm->bna[1] = ab - (float)mean * r * ag;
                    sts_rel_s32(&sm->flagA, t);
                }
            }
            while (lds_acq_s32(&sm->flagA) != t) { }
        }
        float bn4 = sm->bna[0], bn5 = sm->bna[1];

        // ---- straight-through select (argmax, first-index ties) ----
        float score = (raw * bn4 + bn5) * dfac;
        float best = score; int bj = lane;
        #pragma unroll
        for (int o = 16; o; o >>= 1) {
            float os = __shfl_down_sync(F, best, o);
            int   oj = __shfl_down_sync(F, bj, o);
            if (os > best || (os == best && oj < bj)) { best = os; bj = oj; }
        }
        bj = __shfl_sync(F, bj, 0);
        int gsel = __shfl_sync(F, myg, bj);
        float c1 = sm->pv[w][bj][lane];
        float c2 = sm->pv[w][bj][32 + lane];
        cur1 = c1; cur2 = c2;
        sm->cur[w][lane]      = c1;
        sm->cur[w][lane + 32] = c2;
        g_curve[cid][t][lane]      = c1;
        g_curve[cid][t][lane + 32] = c2;
        __syncwarp();

        if (t < CLEN - 1) {
            int nidx = idx[(size_t)gsel * KNBR + lane];   // prefetch next idx row

            // ---- momentum push (decomposed R6 form): shfl + precomputed pre-part ----
            float m0 = __shfl_sync(F, dm0, bj) + pdot0;
            float m1 = __shfl_sync(F, dm1, bj) + pdot1;
            if (lane == 0) {
                g_mm[b * 512 + j]       = m0;
                g_mm[b * 512 + 256 + j] = m1;
                sm->red_m[w][0] = (double)m0; sm->red_m[w][1] = (double)m0 * m0;
                sm->red_m[w][2] = (double)m1; sm->red_m[w][3] = (double)m1 * m1;
            }
            int slot = 2 * t + 1;
            if (w == 0) {
                BAR_SYNC(2);
                double r0 = (lane < WPB) ? sm->red_m[lane][0] : 0.0;
                double r1 = (lane < WPB) ? sm->red_m[lane][1] : 0.0;
                double r2 = (lane < WPB) ? sm->red_m[lane][2] : 0.0;
                double r3 = (lane < WPB) ? sm->red_m[lane][3] : 0.0;
                warpsumd2(r0, r1); warpsumd2(r2, r3);
                if (lane == 0) {
                    long long L0 = __double2ll_rn(r0 * SCALE_S);
                    long long L1 = __double2ll_rn(r1 * SCALE_Q);
                    long long L2 = __double2ll_rn(r2 * SCALE_S);
                    long long L3 = __double2ll_rn(r3 * SCALE_Q);
                    atomicAdd(&g_rsum[slot][0][0], (unsigned long long)L0);
                    atomicAdd(&g_rsum[slot][1][0], (unsigned long long)L1);
                    atomicAdd(&g_rsum[slot][2][0], (unsigned long long)L2);
                    atomicAdd(&g_rsum[slot][3][0], (unsigned long long)L3);
                    __threadfence();
                    red_release_add_u32(&g_rcnt[slot][0], 1u);
                }
            } else {
                BAR_ARRIVE(2);
            }

            // ---- gather next step's neighbor rows (overlaps momentum reduce) ----
            myg = b * NPTS + nidx;
            mypaw = g_paw[myg];
            #pragma unroll
            for (int p = 0; p < 8; ++p) {
                int row = p * 4 + rg;
                int g = __shfl_sync(F, myg, row);
                const float4* src = (const float4*)&g_xw[(size_t)g * C];
                float4 v0 = src[q];
                float4 v1 = src[8 + q];
                *(float4*)&sm->pv[w][row][q * 4]      = v0;
                *(float4*)&sm->pv[w][row][32 + q * 4] = v1;
            }
            __syncwarp();
        }
    }

    // ---- epilogue: per-warp transpose of the curve tile, fully coalesced out ----
    __syncwarp();
    {
        const float4* src = (const float4*)&g_curve[cid][lane][0];
        #pragma unroll
        for (int i = 0; i < 16; ++i) {
            float4 v = src[i];
            *(float4*)&sm->pv[w][lane][i * 4] = v;
        }
        __syncwarp();
        #pragma unroll
        for (int h = 0; h < 2; ++h) {
            int c = lane + h * 32;
            size_t obase = (((size_t)(b * C + c)) * CN + j) * CLEN;
            #pragma unroll
            for (int tc = 0; tc < 8; ++tc) {
                float4 v;
                v.x = sm->pv[w][tc * 4 + 0][c];
                v.y = sm->pv[w][tc * 4 + 1][c];
                v.z = sm->pv[w][tc * 4 + 2][c];
                v.w = sm->pv[w][tc * 4 + 3][c];
                *(float4*)&out[obase + tc * 4] = v;
            }
        }
    }
}

// ---------------- host ----------------
extern "C" void kernel_launch(void* const* d_in, const int* in_sizes, int n_in,
                              void* d_out, int out_size) {
    (void)in_sizes; (void)n_in; (void)out_size;
    const float* x       = (const float*)d_in[0];
    /* d_in[1] = xyz (unused by reference) */
    const int*   idx     = (const int*)d_in[2];
    const float* att_w   = (const float*)d_in[3];
    const float* agent_w = (const float*)d_in[4];
    const float* agent_g = (const float*)d_in[5];
    const float* agent_b = (const float*)d_in[6];
    const float* mom_w   = (const float*)d_in[7];
    const float* mom_g   = (const float*)d_in[8];
    const float* mom_b   = (const float*)d_in[9];
    float* out = (float*)d_out;

    cudaFuncSetAttribute(k_topk, cudaFuncAttributeMaxDynamicSharedMemorySize, NPTS * 8);
    cudaFuncSetAttribute(k_walk, cudaFuncAttributeMaxDynamicSharedMemorySize, (int)sizeof(SW));

    k_xw<<<BNB * 256, 256>>>(x, att_w, agent_w);
    k_topk<<<BNB, 1024, NPTS * 8>>>();
    k_walk<<<WBLK, WTPB, sizeof(SW)>>>(idx, agent_w, agent_g, agent_b,
                                       mom_w, mom_g, mom_b, out);
}